// round 1
// baseline (speedup 1.0000x reference)
#include <cuda_runtime.h>
#include <math.h>

#define BB 8
#define CC 19
#define HH 256
#define WW 256
#define HW (HH*WW)
#define NPIX (BB*HW)
#define TJ 8
#define NCOLBLK (BB*(WW/TJ))
#define INF_F 1e6f

__device__ float g_g2[NPIX];        // squared row distance
__device__ float g_ce[NPIX];        // per-pixel cross entropy
__device__ int   g_flags[BB];       // per-image has-boundary flag
__device__ float g_partial[NCOLBLK];

// ---------------------------------------------------------------------------
// Zero the per-image flags
// ---------------------------------------------------------------------------
__global__ void k_zero() {
    if (threadIdx.x < BB) g_flags[threadIdx.x] = 0;
}

// ---------------------------------------------------------------------------
// Boundary detection (3x3 morphological gradient, edge padding) + exact
// per-row distance to nearest boundary column via bitmask + clz/ffs scan.
// One block per (b, h) row, 256 threads = one per column.
// ---------------------------------------------------------------------------
__global__ void k_boundary(const int* __restrict__ tgt) {
    int bh = blockIdx.x;
    int b  = bh >> 8;
    int h  = bh & 255;
    int j  = threadIdx.x;

    __shared__ int rows[3][WW];
    __shared__ unsigned mask[WW / 32];

    int hu = max(h - 1, 0), hd = min(h + 1, HH - 1);
    const int* base = tgt + b * HW;
    rows[0][j] = base[hu * WW + j];
    rows[1][j] = base[h  * WW + j];
    rows[2][j] = base[hd * WW + j];
    __syncthreads();

    int jl = max(j - 1, 0), jr = min(j + 1, WW - 1);
    int v0 = rows[0][jl], v1 = rows[0][j], v2 = rows[0][jr];
    int v3 = rows[1][jl], v4 = rows[1][j], v5 = rows[1][jr];
    int v6 = rows[2][jl], v7 = rows[2][j], v8 = rows[2][jr];
    int mn = min(min(min(v0, v1), min(v2, v3)), min(min(v4, v5), min(min(v6, v7), v8)));
    int mx = max(max(max(v0, v1), max(v2, v3)), max(max(v4, v5), max(max(v6, v7), v8)));
    bool bd = (mx != mn);

    unsigned bal = __ballot_sync(0xffffffffu, bd);
    if ((j & 31) == 0) mask[j >> 5] = bal;
    __syncthreads();

    // nearest set bit (boundary column) on each side
    int wj = j >> 5, bj = j & 31;
    int dist = 0x7fffffff;

    // left side: bits 0..bj of word wj, then lower words
    {
        unsigned m = mask[wj] & (0xffffffffu >> (31 - bj));
        int w = wj;
        for (;;) {
            if (m) { int pos = (w << 5) + 31 - __clz(m); dist = min(dist, j - pos); break; }
            if (--w < 0) break;
            m = mask[w];
        }
    }
    // right side: bits bj..31 of word wj, then higher words
    {
        unsigned m = mask[wj] & (0xffffffffu << bj);
        int w = wj;
        for (;;) {
            if (m) { int pos = (w << 5) + __ffs(m) - 1; dist = min(dist, pos - j); break; }
            if (++w >= WW / 32) break;
            m = mask[w];
        }
    }

    float g = (dist == 0x7fffffff) ? INF_F : (float)dist;
    g_g2[b * HW + h * WW + j] = g * g;

    if (j == 0) {
        unsigned any = 0;
        #pragma unroll
        for (int w = 0; w < WW / 32; w++) any |= mask[w];
        if (any) atomicOr(&g_flags[b], 1);
    }
}

// ---------------------------------------------------------------------------
// Cross entropy per pixel: ce = logsumexp_c(x) - x[target]
// One thread per pixel, 19 coalesced strided channel loads.
// ---------------------------------------------------------------------------
__global__ void k_ce(const float* __restrict__ x, const int* __restrict__ tgt) {
    int p = blockIdx.x * blockDim.x + threadIdx.x;
    int b = p / HW;
    int rem = p - b * HW;
    const float* px = x + b * (CC * HW) + rem;

    int t = tgt[p];
    float v[CC];
    #pragma unroll
    for (int c = 0; c < CC; c++) v[c] = px[c * HW];

    float m = v[0];
    #pragma unroll
    for (int c = 1; c < CC; c++) m = fmaxf(m, v[c]);

    float s = 0.f, xt = 0.f;
    #pragma unroll
    for (int c = 0; c < CC; c++) {
        s += __expf(v[c] - m);
        if (c == t) xt = v[c];
    }
    g_ce[p] = m + __logf(s) - xt;
}

// ---------------------------------------------------------------------------
// Column pass of exact EDT via expanding-ring search, fused with
// w = exp(-dist/sigma), multiply by ce, and block-level partial reduction.
// Block = (b, 8-column tile), 256 threads; thread (tx=col, ty) handles 8 rows.
// ---------------------------------------------------------------------------
__global__ void k_col() {
    int blk = blockIdx.x;
    int b  = blk / (WW / TJ);
    int j0 = (blk % (WW / TJ)) * TJ;

    __shared__ float g2s[HH][TJ];     // 8 KB
    int tid = threadIdx.x;
    int tx = tid & (TJ - 1);
    int ty = tid >> 3;                // 0..31

    // load g2 tile (32B sector per row chunk, fully coalesced)
    for (int e = tid; e < HH * TJ; e += 256) {
        int k = e >> 3, c = e & (TJ - 1);
        g2s[k][c] = g_g2[b * HW + k * WW + j0 + c];
    }
    __syncthreads();

    int flag = g_flags[b];
    float acc = 0.f;

    #pragma unroll
    for (int rr = 0; rr < 8; rr++) {
        int i = ty + 32 * rr;
        float cur = g2s[i][tx];
        for (int r = 1; r < HH; r++) {
            float r2 = (float)(r * r);
            if (r2 >= cur) break;
            int lo = i - r, hi = i + r;
            if (lo >= 0) cur = fminf(cur, r2 + g2s[lo][tx]);
            if (hi < HH) cur = fminf(cur, r2 + g2s[hi][tx]);
        }
        float wgt = flag ? __expf(-sqrtf(cur) * 0.2f) : 1.0f;
        acc += wgt * g_ce[b * HW + i * WW + j0 + tx];
    }

    __shared__ float red[256];
    red[tid] = acc;
    __syncthreads();
    #pragma unroll
    for (int s = 128; s > 0; s >>= 1) {
        if (tid < s) red[tid] += red[tid + s];
        __syncthreads();
    }
    if (tid == 0) g_partial[blk] = red[0];
}

// ---------------------------------------------------------------------------
// Final deterministic reduction: mean over all pixels
// ---------------------------------------------------------------------------
__global__ void k_final(float* __restrict__ out) {
    __shared__ float red[NCOLBLK];
    int tid = threadIdx.x;
    red[tid] = g_partial[tid];
    __syncthreads();
    #pragma unroll
    for (int s = NCOLBLK / 2; s > 0; s >>= 1) {
        if (tid < s) red[tid] += red[tid + s];
        __syncthreads();
    }
    if (tid == 0) out[0] = red[0] * (1.0f / (float)NPIX);
}

extern "C" void kernel_launch(void* const* d_in, const int* in_sizes, int n_in,
                              void* d_out, int out_size) {
    const float* x   = (const float*)d_in[0];
    const int*   tgt = (const int*)d_in[1];
    float* out = (float*)d_out;

    k_zero<<<1, 32>>>();
    k_boundary<<<BB * HH, WW>>>(tgt);
    k_ce<<<NPIX / 256, 256>>>(x, tgt);
    k_col<<<NCOLBLK, 256>>>();
    k_final<<<1, NCOLBLK>>>(out);
}

// round 2
// speedup vs baseline: 1.2424x; 1.2424x over previous
#include <cuda_runtime.h>
#include <math.h>

#define BB 8
#define CC 19
#define HH 256
#define WW 256
#define HW (HH*WW)
#define NPIX (BB*HW)
#define INF_F 1e6f

#define FUSED_BLOCKS (NPIX / 512)   // 2 pixels/thread, 256 threads -> 4096 blocks... (NPIX=524288)/512=1024

__device__ float g_g2[NPIX];          // squared row distance
__device__ int   g_flags[BB];         // per-image has-boundary flag
__device__ float g_partial[FUSED_BLOCKS];

// ---------------------------------------------------------------------------
// Zero the per-image flags
// ---------------------------------------------------------------------------
__global__ void k_zero() {
    if (threadIdx.x < BB) g_flags[threadIdx.x] = 0;
}

// ---------------------------------------------------------------------------
// Boundary detection (3x3 morphological gradient, edge padding) + exact
// per-row distance to nearest boundary column via bitmask + clz/ffs scan.
// One block per (b, h) row, 256 threads = one per column.
// ---------------------------------------------------------------------------
__global__ void k_boundary(const int* __restrict__ tgt) {
    int bh = blockIdx.x;
    int b  = bh >> 8;
    int h  = bh & 255;
    int j  = threadIdx.x;

    __shared__ int rows[3][WW];
    __shared__ unsigned mask[WW / 32];

    int hu = max(h - 1, 0), hd = min(h + 1, HH - 1);
    const int* base = tgt + b * HW;
    rows[0][j] = base[hu * WW + j];
    rows[1][j] = base[h  * WW + j];
    rows[2][j] = base[hd * WW + j];
    __syncthreads();

    int jl = max(j - 1, 0), jr = min(j + 1, WW - 1);
    int v0 = rows[0][jl], v1 = rows[0][j], v2 = rows[0][jr];
    int v3 = rows[1][jl], v4 = rows[1][j], v5 = rows[1][jr];
    int v6 = rows[2][jl], v7 = rows[2][j], v8 = rows[2][jr];
    int mn = min(min(min(v0, v1), min(v2, v3)), min(min(v4, v5), min(min(v6, v7), v8)));
    int mx = max(max(max(v0, v1), max(v2, v3)), max(max(v4, v5), max(max(v6, v7), v8)));
    bool bd = (mx != mn);

    unsigned bal = __ballot_sync(0xffffffffu, bd);
    if ((j & 31) == 0) mask[j >> 5] = bal;
    __syncthreads();

    int wj = j >> 5, bj = j & 31;
    int dist = 0x7fffffff;

    // left: bits 0..bj of word wj, then lower words
    {
        unsigned m = mask[wj] & (0xffffffffu >> (31 - bj));
        int w = wj;
        for (;;) {
            if (m) { int pos = (w << 5) + 31 - __clz(m); dist = min(dist, j - pos); break; }
            if (--w < 0) break;
            m = mask[w];
        }
    }
    // right: bits bj..31 of word wj, then higher words
    {
        unsigned m = mask[wj] & (0xffffffffu << bj);
        int w = wj;
        for (;;) {
            if (m) { int pos = (w << 5) + __ffs(m) - 1; dist = min(dist, pos - j); break; }
            if (++w >= WW / 32) break;
            m = mask[w];
        }
    }

    float g = (dist == 0x7fffffff) ? INF_F : (float)dist;
    g_g2[b * HW + h * WW + j] = g * g;

    if (j == 0) {
        unsigned any = 0;
        #pragma unroll
        for (int w = 0; w < WW / 32; w++) any |= mask[w];
        if (any) atomicOr(&g_flags[b], 1);
    }
}

// ---------------------------------------------------------------------------
// Fused: cross-entropy (2 pixels/thread, float2 channel loads) + column pass
// of exact EDT via expanding-ring search over g_g2 + weight + block reduce.
// ---------------------------------------------------------------------------
__global__ void __launch_bounds__(256) k_fused(const float* __restrict__ x,
                                               const int* __restrict__ tgt) {
    int t = blockIdx.x * blockDim.x + threadIdx.x;  // handles pixels 2t, 2t+1
    int p = t * 2;
    int b = p / HW;
    int rem = p - b * HW;
    int i = rem >> 8;                 // row
    // pixel pair shares row (W even)

    const float2* px = (const float2*)(x + (size_t)b * CC * HW + rem);
    int2 tg = *(const int2*)(tgt + p);

    float2 v[CC];
    #pragma unroll
    for (int c = 0; c < CC; c++) v[c] = px[c * (HW / 2)];

    float m0 = v[0].x, m1 = v[0].y;
    #pragma unroll
    for (int c = 1; c < CC; c++) { m0 = fmaxf(m0, v[c].x); m1 = fmaxf(m1, v[c].y); }

    float s0 = 0.f, s1 = 0.f, xt0 = 0.f, xt1 = 0.f;
    #pragma unroll
    for (int c = 0; c < CC; c++) {
        s0 += __expf(v[c].x - m0);
        s1 += __expf(v[c].y - m1);
        if (c == tg.x) xt0 = v[c].x;
        if (c == tg.y) xt1 = v[c].y;
    }
    float ce0 = m0 + __logf(s0) - xt0;
    float ce1 = m1 + __logf(s1) - xt1;

    // ---- column EDT: d^2(i,j) = min_k (i-k)^2 + g2(k,j), expanding ring ----
    const float2* g2b = (const float2*)(g_g2 + (size_t)b * HW);
    int rowoff = rem >> 1;            // float2 index of (i, j)
    float2 cg = g2b[rowoff];
    float c0 = cg.x, c1 = cg.y;

    for (int r = 1; r < HH; r++) {
        float r2 = (float)(r * r);
        if (r2 >= fmaxf(c0, c1)) break;
        int lo = i - r, hi = i + r;
        if (lo >= 0) {
            float2 nb = g2b[rowoff + lo * (WW / 2) - i * (WW / 2)];
            c0 = fminf(c0, r2 + nb.x); c1 = fminf(c1, r2 + nb.y);
        }
        if (hi < HH) {
            float2 nb = g2b[rowoff + hi * (WW / 2) - i * (WW / 2)];
            c0 = fminf(c0, r2 + nb.x); c1 = fminf(c1, r2 + nb.y);
        }
    }

    float acc;
    if (g_flags[b]) {
        float w0 = __expf(-sqrtf(c0) * 0.2f);
        float w1 = __expf(-sqrtf(c1) * 0.2f);
        acc = w0 * ce0 + w1 * ce1;
    } else {
        acc = ce0 + ce1;
    }

    // block reduction
    __shared__ float red[256];
    int tid = threadIdx.x;
    // warp shuffle first
    #pragma unroll
    for (int o = 16; o > 0; o >>= 1) acc += __shfl_down_sync(0xffffffffu, acc, o);
    if ((tid & 31) == 0) red[tid >> 5] = acc;
    __syncthreads();
    if (tid < 8) {
        float s = red[tid];
        #pragma unroll
        for (int o = 4; o > 0; o >>= 1) s += __shfl_down_sync(0xffu, s, o);
        if (tid == 0) g_partial[blockIdx.x] = s;
    }
}

// ---------------------------------------------------------------------------
// Final deterministic reduction: mean over all pixels
// ---------------------------------------------------------------------------
__global__ void k_final(float* __restrict__ out) {
    __shared__ float red[1024];
    int tid = threadIdx.x;
    red[tid] = g_partial[tid];
    __syncthreads();
    #pragma unroll
    for (int s = 512; s > 0; s >>= 1) {
        if (tid < s) red[tid] += red[tid + s];
        __syncthreads();
    }
    if (tid == 0) out[0] = red[0] * (1.0f / (float)NPIX);
}

extern "C" void kernel_launch(void* const* d_in, const int* in_sizes, int n_in,
                              void* d_out, int out_size) {
    const float* x   = (const float*)d_in[0];
    const int*   tgt = (const int*)d_in[1];
    float* out = (float*)d_out;

    k_zero<<<1, 32>>>();
    k_boundary<<<BB * HH, WW>>>(tgt);
    k_fused<<<FUSED_BLOCKS, 256>>>(x, tgt);
    k_final<<<1, FUSED_BLOCKS>>>(out);
}